// round 5
// baseline (speedup 1.0000x reference)
#include <cuda_runtime.h>
#include <cuda_fp16.h>
#include <cstdint>

#define DEVFN static __device__ __forceinline__

namespace edk {

constexpr int NB = 2, NN = 512, NE = 128, NH = 256;
constexpr int NTILES = NB * NN * 4;   // 4096 tiles of 128 j's

constexpr int APH = 272;              // A half-tile row stride (bytes): conflict-free ldmatrix
constexpr int AHALF = 128 * APH;      // 34816 bytes per K-half A buffer
constexpr int BP = 528;               // B tile row stride (bytes)

// dynamic smem layout (shared by both passes)
constexpr uint32_t MS_PB  = 0;      // pass1: PB 256 f32   | pass2: b2 256 f32
constexpr uint32_t MS_W1D = 1024;   // pass1: w1d 256 f32  | pass2: W3 256 f32
constexpr uint32_t MS_D   = 2048;   // pass1: d col 128 f32| pass2: red 128 f32
constexpr uint32_t MS_HI  = 2560;   // pass1: h_i 128 fp16
constexpr uint32_t MS_T   = 2944;   // stolen tile index (4B)
constexpr uint32_t SMA    = 4096;                 // A: two K-halves, 2*34816
constexpr uint32_t SMB    = SMA + 2 * AHALF;      // 73728; B: 256 x 528 = 135168
constexpr uint32_t SMEM_TOTAL = SMB + 256 * BP;   // 208896

constexpr int GRID = 152;

// ---- device scratch ----
__device__ __align__(16) __half g_hf16[NB * NN * NE];
__device__ __align__(16) __half g_B1f16[NH * NH];   // [k][n]: k<128 -> W1[256+k][n], else W1[k][n]
__device__ __align__(16) __half g_W2f16[NH * NH];   // [k][n] = W2[k][n]
__device__ float g_PB[NB * NN * NH];                // h_i . W1a + b1 (fp32 exact)
__device__ __align__(16) __half g_h1[(size_t)NTILES * 2 * 128 * 128];  // 256MB intermediate
__device__ float g_raw[NB * NN * NN];
__device__ unsigned g_cnt1, g_cnt2;

// ---- helpers ----
DEVFN uint32_t smem_u32(const void* p) {
    uint32_t a;
    asm("{ .reg .u64 t; cvta.to.shared.u64 t, %1; cvt.u32.u64 %0, t; }" : "=r"(a) : "l"(p));
    return a;
}
DEVFN void cp16(uint32_t dst, const void* src) {
    asm volatile("cp.async.cg.shared.global [%0], [%1], 16;" :: "r"(dst), "l"(src) : "memory");
}
DEVFN void cp_commit() { asm volatile("cp.async.commit_group;" ::: "memory"); }
DEVFN void cp_wait0()  { asm volatile("cp.async.wait_group 0;" ::: "memory"); }
DEVFN void cp_wait1()  { asm volatile("cp.async.wait_group 1;" ::: "memory"); }

DEVFN void ldm_x4(uint32_t* r, uint32_t addr) {
    asm volatile("ldmatrix.sync.aligned.m8n8.x4.shared.b16 {%0,%1,%2,%3}, [%4];"
                 : "=r"(r[0]), "=r"(r[1]), "=r"(r[2]), "=r"(r[3]) : "r"(addr));
}
DEVFN void ldm_x4_t(uint32_t* r, uint32_t addr) {
    asm volatile("ldmatrix.sync.aligned.m8n8.x4.trans.shared.b16 {%0,%1,%2,%3}, [%4];"
                 : "=r"(r[0]), "=r"(r[1]), "=r"(r[2]), "=r"(r[3]) : "r"(addr));
}
DEVFN void mma16816(float* d, const uint32_t* a, const uint32_t* b) {
    asm volatile(
        "mma.sync.aligned.m16n8k16.row.col.f32.f16.f16.f32 "
        "{%0,%1,%2,%3}, {%4,%5,%6,%7}, {%8,%9}, {%0,%1,%2,%3};"
        : "+f"(d[0]), "+f"(d[1]), "+f"(d[2]), "+f"(d[3])
        : "r"(a[0]), "r"(a[1]), "r"(a[2]), "r"(b[0]), "r"(a[3]), "r"(b[1]));
}
// NOTE: operand order above must match {a0,a1,a2,a3},{b0,b1}; fix inline:
DEVFN void mma_fix(float* d, const uint32_t* a, const uint32_t* b) {
    asm volatile(
        "mma.sync.aligned.m16n8k16.row.col.f32.f16.f16.f32 "
        "{%0,%1,%2,%3}, {%4,%5,%6,%7}, {%8,%9}, {%0,%1,%2,%3};"
        : "+f"(d[0]), "+f"(d[1]), "+f"(d[2]), "+f"(d[3])
        : "r"(a[0]), "r"(a[1]), "r"(a[2]), "r"(a[3]), "r"(b[0]), "r"(b[1]));
}

// K=128 GEMM chunk: warp tile 64m x 64n, A half-buffer (stride APH), B rows (stride BP)
DEVFN void gemm_k128(uint32_t A0, uint32_t B0, float (&acc)[4][8][4]) {
#pragma unroll 2
    for (int kk = 0; kk < 8; kk++) {
        uint32_t a[4][4], bf[4][4];
#pragma unroll
        for (int tm = 0; tm < 4; tm++) ldm_x4(a[tm], A0 + tm * (16 * APH) + kk * 32);
#pragma unroll
        for (int tn = 0; tn < 4; tn++) ldm_x4_t(bf[tn], B0 + kk * (16 * BP) + tn * 32);
#pragma unroll
        for (int tm = 0; tm < 4; tm++)
#pragma unroll
            for (int tn = 0; tn < 8; tn++)
                mma_fix(acc[tm][tn], a[tm], &bf[tn >> 1][(tn & 1) * 2]);
    }
}
DEVFN void zero_acc(float (&acc)[4][8][4]) {
#pragma unroll
    for (int x = 0; x < 4; x++)
#pragma unroll
        for (int y = 0; y < 8; y++)
#pragma unroll
            for (int z = 0; z < 4; z++) acc[x][y][z] = 0.0f;
}
// load a 256x256 fp16 weight image (512B rows) into smem B tile (528B rows)
DEVFN void load_B(uint32_t sb, const __half* img, int tid) {
    const char* src = (const char*)img;
#pragma unroll
    for (int it = 0; it < 32; it++) {
        int id = tid + it * 256;
        int r = id >> 5, c = id & 31;
        cp16(sb + SMB + r * BP + c * 16, src + r * 512 + c * 16);
    }
    cp_commit();
}

// ---- prep kernels ----
__global__ void prep_all(const float* __restrict__ node, const float* __restrict__ W1,
                         const float* __restrict__ W2) {
    int bidx = blockIdx.x;
    if (bidx == 0 && threadIdx.x == 0) { g_cnt1 = 0; g_cnt2 = 0; }
    if (bidx < 512) {
        int idx = bidx * 256 + threadIdx.x;
        g_hf16[idx] = __float2half_rn(node[idx]);
    } else if (bidx < 768) {
        int idx = (bidx - 512) * 256 + threadIdx.x;
        int k = idx >> 8, n = idx & 255;
        float v = (k < 128) ? W1[(256 + k) * NH + n] : W1[k * NH + n];
        g_B1f16[idx] = __float2half_rn(v);
    } else {
        int idx = (bidx - 768) * 256 + threadIdx.x;
        g_W2f16[idx] = __float2half_rn(W2[idx]);
    }
}
// PB: 8 bi-rows per CTA, W1 streamed once per CTA
__global__ void prep_PB(const float* __restrict__ node, const float* __restrict__ W1,
                        const float* __restrict__ b1) {
    __shared__ float rows[8][NE];
    int bi0 = blockIdx.x * 8;
    for (int idx = threadIdx.x; idx < 8 * NE; idx += 256)
        rows[idx >> 7][idx & 127] = node[(size_t)bi0 * NE + idx];
    __syncthreads();
    int h = threadIdx.x;
    float acc[8];
    float bv = b1[h];
#pragma unroll
    for (int r = 0; r < 8; r++) acc[r] = bv;
#pragma unroll 4
    for (int k = 0; k < NE; k++) {
        float w = W1[k * NH + h];
#pragma unroll
        for (int r = 0; r < 8; r++) acc[r] = fmaf(rows[r][k], w, acc[r]);
    }
#pragma unroll
    for (int r = 0; r < 8; r++) g_PB[(size_t)(bi0 + r) * NH + h] = acc[r];
}

// ---- pass 1: persistent; B1 resident; per tile build A, GEMM1, epilogue -> g_h1 ----
__global__ void __launch_bounds__(256, 1)
pass1(const float* __restrict__ euclid, const float* __restrict__ W1) {
    extern __shared__ char smem[];
    uint32_t sb = smem_u32(smem);
    int tid = threadIdx.x, wid = tid >> 5, lane = tid & 31;
    int mb = (wid & 1) * 64, nb = (wid >> 1) * 64;
    int g = lane >> 2, t4 = lane & 3;
    uint32_t Abase = sb + SMA + (mb + (lane & 15)) * APH + (lane >> 4) * 16;
    uint32_t Bbase = sb + SMB + (lane & 15) * BP + nb * 2 + (lane >> 4) * 16;

    load_B(sb, g_B1f16, tid);
    ((float*)(smem + MS_W1D))[tid] = W1[384 * NH + tid];
    cp_wait0();

    float acc[4][8][4];
    for (;;) {
        if (tid == 0) *(volatile unsigned*)(smem + MS_T) = atomicAdd(&g_cnt1, 1u);
        __syncthreads();                       // prev epilogue done + tile published
        int t = (int)*(volatile unsigned*)(smem + MS_T);
        if (t >= NTILES) break;
        int bi = t >> 2;
        // per-tile small loads
        ((float*)(smem + MS_PB))[tid] = g_PB[(size_t)bi * NH + tid];
        if (tid < 128) ((float*)(smem + MS_D))[tid] = euclid[(size_t)t * 128 + tid];
        if (tid < 64)
            ((uint32_t*)(smem + MS_HI))[tid] = ((const uint32_t*)g_hf16)[(size_t)bi * 64 + tid];
        __syncthreads();
        // build A: half0 = |h_i - h_j|, half1 = h_j
        {
            int r = tid >> 1, hh = tid & 1;
            int jrow = ((bi >> 9) << 9) + ((t & 3) << 7) + r;
            const uint4* hj  = (const uint4*)(g_hf16 + (size_t)jrow * NE) + hh * 8;
            const uint4* hip = (const uint4*)(smem + MS_HI) + hh * 8;
            char* A0p = smem + SMA + r * APH + hh * 128;
            char* A1p = A0p + AHALF;
#pragma unroll
            for (int u = 0; u < 8; u++) {
                uint4 jv = hj[u], iv = hip[u], ab;
                const __half2* jp = (const __half2*)&jv;
                const __half2* ip = (const __half2*)&iv;
                __half2* ap = (__half2*)&ab;
#pragma unroll
                for (int e = 0; e < 4; e++) ap[e] = __habs2(__hsub2(ip[e], jp[e]));
                *(uint4*)(A0p + u * 16) = ab;
                *(uint4*)(A1p + u * 16) = jv;
            }
        }
        __syncthreads();
        zero_acc(acc);
        gemm_k128(Abase, Bbase, acc);
        gemm_k128(Abase + AHALF, Bbase + 8 * 16 * BP, acc);
        // epilogue1: + PB + d*w1d, relu, fp16 -> g_h1 (tile-major, K-split halves)
        {
            const float* PBs  = (const float*)(smem + MS_PB);
            const float* w1ds = (const float*)(smem + MS_W1D);
            const float* ds   = (const float*)(smem + MS_D);
            __half* h1b = g_h1 + (size_t)t * 32768;
#pragma unroll
            for (int tm = 0; tm < 4; tm++) {
                int r0 = mb + tm * 16 + g;
                float d0 = ds[r0], d1 = ds[r0 + 8];
#pragma unroll
                for (int tn = 0; tn < 8; tn++) {
                    int c = nb + tn * 8 + t4 * 2;
                    float pb0 = PBs[c], pb1 = PBs[c + 1];
                    float w0 = w1ds[c], w1v = w1ds[c + 1];
                    float v0 = fmaxf(fmaf(d0, w0,  acc[tm][tn][0] + pb0), 0.0f);
                    float v1 = fmaxf(fmaf(d0, w1v, acc[tm][tn][1] + pb1), 0.0f);
                    float v2 = fmaxf(fmaf(d1, w0,  acc[tm][tn][2] + pb0), 0.0f);
                    float v3 = fmaxf(fmaf(d1, w1v, acc[tm][tn][3] + pb1), 0.0f);
                    __half* p = h1b + (c >> 7) * 16384 + r0 * 128 + (c & 127);
                    *(__half2*)p             = __floats2half2_rn(v0, v1);
                    *(__half2*)(p + 8 * 128) = __floats2half2_rn(v2, v3);
                }
            }
        }
    }
}

// ---- pass 2: persistent; W2 resident; h1 streamed with K-chunk double buffering ----
DEVFN void pf_h1(uint32_t sb, int t, int half, int tid) {
    if (t < NTILES) {
        const char* src = (const char*)(g_h1 + ((size_t)t * 2 + half) * 16384);
        uint32_t dst = sb + SMA + half * AHALF;
#pragma unroll
        for (int it = 0; it < 8; it++) {
            int id = tid + it * 256;
            int r = id >> 4, c = id & 15;
            cp16(dst + r * APH + c * 16, src + r * 256 + c * 16);
        }
    }
    cp_commit();
}

__global__ void __launch_bounds__(256, 1)
pass2(const float* __restrict__ b2, const float* __restrict__ W3,
      const float* __restrict__ b3) {
    extern __shared__ char smem[];
    uint32_t sb = smem_u32(smem);
    int tid = threadIdx.x, wid = tid >> 5, lane = tid & 31;
    int mb = (wid & 1) * 64, nb = (wid >> 1) * 64;
    int g = lane >> 2, t4 = lane & 3;
    uint32_t Abase = sb + SMA + (mb + (lane & 15)) * APH + (lane >> 4) * 16;
    uint32_t Bbase = sb + SMB + (lane & 15) * BP + nb * 2 + (lane >> 4) * 16;

    load_B(sb, g_W2f16, tid);                      // group: W2
    ((float*)(smem + MS_PB))[tid]  = b2[tid];      // MS_PB slot = b2
    ((float*)(smem + MS_W1D))[tid] = W3[tid];      // MS_W1D slot = W3
    float b3v = b3[0];

    int t;
    if (tid == 0) *(volatile unsigned*)(smem + MS_T) = atomicAdd(&g_cnt2, 1u);
    __syncthreads();
    t = (int)*(volatile unsigned*)(smem + MS_T);
    pf_h1(sb, t, 0, tid);
    pf_h1(sb, t, 1, tid);

    float acc[4][8][4];
    while (t < NTILES) {
        cp_wait1();                 // half0 (and W2) landed
        __syncthreads();
        zero_acc(acc);
        gemm_k128(Abase, Bbase, acc);
        if (tid == 0) *(volatile unsigned*)(smem + MS_T) = atomicAdd(&g_cnt2, 1u);
        __syncthreads();            // half0 reads done + next tile published
        int tn_next = (int)*(volatile unsigned*)(smem + MS_T);
        pf_h1(sb, tn_next, 0, tid);
        cp_wait1();                 // half1 landed
        __syncthreads();
        gemm_k128(Abase + AHALF, Bbase + 8 * 16 * BP, acc);
        __syncthreads();            // half1 reads done
        pf_h1(sb, tn_next, 1, tid);
        // epilogue2: relu(+b2) . W3, reduce, + b3 -> g_raw
        float* red = (float*)(smem + MS_D);
        if (tid < 128) red[tid] = 0.0f;
        __syncthreads();
        {
            const float* b2s = (const float*)(smem + MS_PB);
            const float* w3s = (const float*)(smem + MS_W1D);
            float s[4][2];
#pragma unroll
            for (int tm = 0; tm < 4; tm++) { s[tm][0] = 0.0f; s[tm][1] = 0.0f; }
#pragma unroll
            for (int tm = 0; tm < 4; tm++)
#pragma unroll
                for (int tn = 0; tn < 8; tn++) {
                    int c = nb + tn * 8 + t4 * 2;
                    float bb0 = b2s[c], bb1 = b2s[c + 1];
                    float w0 = w3s[c], w1v = w3s[c + 1];
                    s[tm][0] = fmaf(fmaxf(acc[tm][tn][0] + bb0, 0.0f), w0,
                               fmaf(fmaxf(acc[tm][tn][1] + bb1, 0.0f), w1v, s[tm][0]));
                    s[tm][1] = fmaf(fmaxf(acc[tm][tn][2] + bb0, 0.0f), w0,
                               fmaf(fmaxf(acc[tm][tn][3] + bb1, 0.0f), w1v, s[tm][1]));
                }
#pragma unroll
            for (int tm = 0; tm < 4; tm++)
#pragma unroll
                for (int h = 0; h < 2; h++) {
                    float v = s[tm][h];
                    v += __shfl_xor_sync(0xffffffffu, v, 1);
                    v += __shfl_xor_sync(0xffffffffu, v, 2);
                    if (t4 == 0) atomicAdd(red + mb + tm * 16 + g + h * 8, v);
                }
        }
        __syncthreads();
        if (tid < 128) g_raw[(size_t)t * 128 + tid] = red[tid] + b3v;
        t = tn_next;
    }
    cp_wait0();
}

// ---- symmetrize + zero diagonal ----
__global__ void sym_kernel(float* __restrict__ out) {
    int idx = blockIdx.x * 256 + threadIdx.x;  // 524288
    int bb = idx >> 18;
    int rem = idx & (NN * NN - 1);
    int i = rem >> 9, j = rem & 511;
    float v = (i == j) ? 0.0f
                       : 0.5f * (g_raw[idx] + g_raw[(bb << 18) + (j << 9) + i]);
    out[idx] = v;
}

}  // namespace edk

extern "C" void kernel_launch(void* const* d_in, const int* in_sizes, int n_in,
                              void* d_out, int out_size) {
    (void)in_sizes; (void)n_in; (void)out_size;
    using namespace edk;
    const float* node   = (const float*)d_in[0];
    // d_in[1] = problems (unused; euclid matrix provided)
    const float* euclid = (const float*)d_in[2];
    const float* W1 = (const float*)d_in[3];
    const float* b1 = (const float*)d_in[4];
    const float* W2 = (const float*)d_in[5];
    const float* b2 = (const float*)d_in[6];
    const float* W3 = (const float*)d_in[7];
    const float* b3 = (const float*)d_in[8];
    float* out = (float*)d_out;

    cudaFuncSetAttribute(pass1, cudaFuncAttributeMaxDynamicSharedMemorySize, SMEM_TOTAL);
    cudaFuncSetAttribute(pass2, cudaFuncAttributeMaxDynamicSharedMemorySize, SMEM_TOTAL);

    prep_all<<<1024, 256>>>(node, W1, W2);
    prep_PB<<<128, 256>>>(node, W1, b1);
    pass1<<<GRID, 256, SMEM_TOTAL>>>(euclid, W1);
    pass2<<<GRID, 256, SMEM_TOTAL>>>(b2, W3, b3);
    sym_kernel<<<2048, 256>>>(out);
}